// round 1
// baseline (speedup 1.0000x reference)
#include <cuda_runtime.h>
#include <math.h>

#define H        4096
#define E        64
#define TM       64      // tokens per block
#define TK       32      // k-chunk
#define NTHREADS 256
#define XPAD     68      // padded row length (bank-conflict-free transposed stores)

// out layout (fp32, concatenated): probs[ntok][64] | top_k_weights[ntok][2] | top_k_index[ntok][2]

__global__ __launch_bounds__(NTHREADS, 2)
void router_kernel(const float* __restrict__ xg,
                   const float* __restrict__ wg,
                   const float* __restrict__ sg,
                   const float* __restrict__ pes,
                   float* __restrict__ out,
                   int ntok)
{
    __shared__ float smem[2 * TK * XPAD];   // 4352 floats: xs | ws ; reused as sc[64][64]
    __shared__ float ssq[TM];
    __shared__ float sums[TM];
    __shared__ float topw[TM * 2];
    __shared__ float topi[TM * 2];

    float (*xs)[XPAD] = reinterpret_cast<float(*)[XPAD]>(smem);
    float (*ws)[XPAD] = reinterpret_cast<float(*)[XPAD]>(smem + TK * XPAD);

    const int tid = threadIdx.x;
    const int tg  = tid >> 4;      // 0..15 : token group (4 tokens)
    const int eg  = tid & 15;      // 0..15 : expert group (4 experts)
    const int tok0 = blockIdx.x * TM;

    if (tid < TM) ssq[tid] = 0.f;

    // tile-load assignment: index i in [0,512) covers (row = i>>3, kq = i&7), rows 0..63
    // thread handles i = tid (rows 0..31) and i = tid+256 (rows 32..63)
    const int rowA = tid >> 3;     // 0..31
    const int kqA  = tid & 7;      // float4 slot within 32-wide k chunk

    const float* xA = xg + (size_t)(tok0 + rowA) * H + kqA * 4;
    const float* xB = xA + (size_t)32 * H;
    const float* wA = wg + (size_t)rowA * H + kqA * 4;   // expert row = rowA
    const float* wB = wA + (size_t)32 * H;
    const float* sA = sg + kqA * 4;

    float ssqA = 0.f, ssqB = 0.f;

    // prologue prefetch (chunk 0)
    float4 xr0 = *(const float4*)xA;
    float4 xr1 = *(const float4*)xB;
    float4 wr0 = *(const float4*)wA;
    float4 wr1 = *(const float4*)wB;
    float4 sr  = *(const float4*)sA;

    float acc[4][4];
    #pragma unroll
    for (int i = 0; i < 4; i++)
        #pragma unroll
        for (int j = 0; j < 4; j++) acc[i][j] = 0.f;

    const int NC = H / TK;   // 128
    for (int c = 0; c < NC; c++) {
        // ---- store prefetched tile to smem (transposed), fold scale into W,
        //      accumulate raw-x sum of squares
        const int kb = kqA * 4;
        xs[kb + 0][rowA] = xr0.x;  xs[kb + 1][rowA] = xr0.y;
        xs[kb + 2][rowA] = xr0.z;  xs[kb + 3][rowA] = xr0.w;
        xs[kb + 0][rowA + 32] = xr1.x;  xs[kb + 1][rowA + 32] = xr1.y;
        xs[kb + 2][rowA + 32] = xr1.z;  xs[kb + 3][rowA + 32] = xr1.w;

        ws[kb + 0][rowA] = wr0.x * sr.x;  ws[kb + 1][rowA] = wr0.y * sr.y;
        ws[kb + 2][rowA] = wr0.z * sr.z;  ws[kb + 3][rowA] = wr0.w * sr.w;
        ws[kb + 0][rowA + 32] = wr1.x * sr.x;  ws[kb + 1][rowA + 32] = wr1.y * sr.y;
        ws[kb + 2][rowA + 32] = wr1.z * sr.z;  ws[kb + 3][rowA + 32] = wr1.w * sr.w;

        ssqA += xr0.x*xr0.x + xr0.y*xr0.y + xr0.z*xr0.z + xr0.w*xr0.w;
        ssqB += xr1.x*xr1.x + xr1.y*xr1.y + xr1.z*xr1.z + xr1.w*xr1.w;

        __syncthreads();

        // ---- prefetch next chunk (latency hidden behind compute below)
        if (c + 1 < NC) {
            const int off = (c + 1) * TK;
            xr0 = *(const float4*)(xA + off);
            xr1 = *(const float4*)(xB + off);
            wr0 = *(const float4*)(wA + off);
            wr1 = *(const float4*)(wB + off);
            sr  = *(const float4*)(sA + off);
        }

        // ---- compute: 32 k-steps, 2 LDS.128 + 16 FFMA each
        #pragma unroll
        for (int kk = 0; kk < TK; kk++) {
            float4 xv = *(const float4*)&xs[kk][tg * 4];
            float4 wv = *(const float4*)&ws[kk][eg * 4];
            float xa[4] = {xv.x, xv.y, xv.z, xv.w};
            float wa[4] = {wv.x, wv.y, wv.z, wv.w};
            #pragma unroll
            for (int i = 0; i < 4; i++)
                #pragma unroll
                for (int j = 0; j < 4; j++)
                    acc[i][j] += xa[i] * wa[j];
        }
        __syncthreads();
    }

    // ---- reduce sum of squares (8 partial owners per token)
    atomicAdd(&ssq[rowA],      ssqA);
    atomicAdd(&ssq[rowA + 32], ssqB);

    // ---- scores to smem (overlays xs/ws; all compute reads done, last sync above)
    float* sc = smem;   // sc[t][e], stride 64, 4096 floats
    #pragma unroll
    for (int i = 0; i < 4; i++) {
        float4 v = make_float4(acc[i][0], acc[i][1], acc[i][2], acc[i][3]);
        *(float4*)&sc[(tg * 4 + i) * 64 + eg * 4] = v;
    }
    __syncthreads();

    // ---- per-token softmax + top-2 (one thread per token)
    if (tid < TM) {
        const int t = tid;
        // inv = rsqrt(mean(x^2)+eps) * H^-0.5
        const float r = 1.0f / (64.0f * sqrtf(ssq[t] * (1.0f / 4096.0f) + 1e-6f));
        float m = -1e30f;
        #pragma unroll 8
        for (int e = 0; e < 64; e++) m = fmaxf(m, sc[t * 64 + e] * r);
        float sum = 0.f;
        float m1 = -1.f, m2 = -1.f;
        int   i1 = 0,   i2 = 0;
        for (int e = 0; e < 64; e++) {
            float ex = __expf(sc[t * 64 + e] * r - m);
            sum += ex;
            sc[t * 64 + e] = ex;
            if (ex > m1)      { m2 = m1; i2 = i1; m1 = ex; i1 = e; }
            else if (ex > m2) { m2 = ex; i2 = e; }
        }
        sums[t] = sum;
        const float denom = 1.0f / (m1 + m2);   // p1/(p1+p2) == e1/(e1+e2)
        topw[t * 2 + 0] = m1 * denom * pes[i1];
        topw[t * 2 + 1] = m2 * denom * pes[i2];
        topi[t * 2 + 0] = (float)i1;
        topi[t * 2 + 1] = (float)i2;
    }
    __syncthreads();

    // ---- coalesced outputs
    float* pout = out + (size_t)tok0 * 64;
    #pragma unroll
    for (int q = 0; q < 4; q++) {
        const int idx = tid + q * 256;          // float4 index, 1024 total
        float4 v = *(const float4*)&sc[idx * 4];
        const float inv = 1.0f / sums[idx >> 4];
        v.x *= inv; v.y *= inv; v.z *= inv; v.w *= inv;
        *(float4*)&pout[idx * 4] = v;
    }
    float* wout = out + (size_t)ntok * 64;
    float* iout = wout + (size_t)ntok * 2;
    if (tid < TM * 2) {
        wout[tok0 * 2 + tid] = topw[tid];
        iout[tok0 * 2 + tid] = topi[tid];
    }
}

extern "C" void kernel_launch(void* const* d_in, const int* in_sizes, int n_in,
                              void* d_out, int out_size)
{
    (void)n_in; (void)out_size;
    const float* x   = (const float*)d_in[0];
    const float* w   = (const float*)d_in[1];
    const float* s   = (const float*)d_in[2];
    const float* pes = (const float*)d_in[3];
    const int ntok = in_sizes[0] / H;           // 16384
    const int grid = ntok / TM;                 // 256
    router_kernel<<<grid, NTHREADS>>>(x, w, s, pes, (float*)d_out, ntok);
}